// round 8
// baseline (speedup 1.0000x reference)
#include <cuda_runtime.h>
#include <cstdint>

// Causal GQA attention via warp-level mma.sync tf32 (plain sm_103 target).
// B=2, S=2048, H=32, HK=8 (rep 4), D=128. fp32 in/out.
// Max-free softmax; Q as register A-fragments; K/V via cp.async pipeline;
// P stays in registers (QK C-frags re-fed as PV A-frags, sigma absorbed in V
// addressing). This round: __launch_bounds__(128,3) -> 3 CTAs/SM (12 warps).

#define SEQ 2048
#define NH 32
#define NHK 8
#define HD 128
#define QSTR (NH*HD)    // 4096
#define KSTR (NHK*HD)   // 1024
#define BQ 64
#define BK 64
#define NTHREADS 128

// smem layout (bytes)
#define SK_OFF 0                      // 64 rows x 512B, swizzled 16B chunks
#define SV_OFF 32768                  // 64 rows x 560B (128f + pad), linear
#define SMEM_BYTES (SV_OFF + 64*560)  // 68608 ; 3 CTAs -> 201KB/SM

static __device__ __forceinline__ uint32_t smem_u32(const void* p){
    uint32_t a;
    asm("{ .reg .u64 t; cvta.to.shared.u64 t, %1; cvt.u32.u64 %0, t; }" : "=r"(a) : "l"(p));
    return a;
}
static __device__ __forceinline__ float tf32r(float x){
    uint32_t u;
    asm("cvt.rna.tf32.f32 %0, %1;" : "=r"(u) : "f"(x));
    return __uint_as_float(u);
}
static __device__ __forceinline__ void ldm4(uint32_t* r, uint32_t addr){
    asm volatile("ldmatrix.sync.aligned.m8n8.x4.shared.b16 {%0,%1,%2,%3}, [%4];"
                 : "=r"(r[0]), "=r"(r[1]), "=r"(r[2]), "=r"(r[3]) : "r"(addr));
}
static __device__ __forceinline__ void mma8(float* d, const uint32_t* a,
                                            uint32_t b0, uint32_t b1){
    asm volatile(
        "mma.sync.aligned.m16n8k8.row.col.f32.tf32.tf32.f32 "
        "{%0,%1,%2,%3}, {%4,%5,%6,%7}, {%8,%9}, {%0,%1,%2,%3};"
        : "+f"(d[0]), "+f"(d[1]), "+f"(d[2]), "+f"(d[3])
        : "r"(a[0]), "r"(a[1]), "r"(a[2]), "r"(a[3]), "r"(b0), "r"(b1));
}
static __device__ __forceinline__ void cpa16(uint32_t dst, const float* base, uint32_t off){
    asm volatile("cp.async.cg.shared.global [%0], [%1], 16;"
                 :: "r"(dst), "l"(base + off));
}
#define CP_COMMIT() asm volatile("cp.async.commit_group;")
#define CP_WAIT(N)  asm volatile("cp.async.wait_group %0;" :: "n"(N))

__global__ __launch_bounds__(NTHREADS, 3)
void fattn_mma(const float* __restrict__ qg, const float* __restrict__ kg,
               const float* __restrict__ vg, float* __restrict__ outg)
{
    extern __shared__ char smem[];
    const uint32_t smb = smem_u32(smem);
    const uint32_t sKb = smb + SK_OFF;
    const uint32_t sVb = smb + SV_OFF;

    const int tid  = threadIdx.x;
    const int lane = tid & 31;
    const int w    = tid >> 5;          // warp 0..3, owns q-rows 16w..16w+15
    const int g    = lane >> 2;
    const int tig  = lane & 3;
    const int mi   = lane >> 3;
    const int r8   = lane & 7;
    const int hiA  = mi >> 1;           // A-frag chunk offset (0/1)
    const int hiB  = lane >> 3;         // B-frag chunk offset (0..3)
    const int rowA = w*16 + (mi & 1)*8 + r8;

    const int qt = (int)(gridDim.x - 1 - blockIdx.x);   // heavy tiles first
    const int h  = blockIdx.y;
    const int b  = blockIdx.z;
    const int hk = h >> 2;
    const int q0 = qt * BQ;

    // ---- build Q A-fragments in registers (staged via sK as scratch) ----
    uint32_t qf[16][4];
    {
        const float qsc = 0.08838834764831845f * 1.4426950408889634f;
        const float* qs = qg + (uint32_t)(b*SEQ + q0)*QSTR + h*HD;
        #pragma unroll
        for (int i = 0; i < 16; i++) {
            int idx = i*NTHREADS + tid;
            int r = idx >> 5, c = idx & 31;
            float4 v = *(const float4*)(qs + (uint32_t)r*QSTR + c*4);
            v.x = tf32r(v.x*qsc); v.y = tf32r(v.y*qsc);
            v.z = tf32r(v.z*qsc); v.w = tf32r(v.w*qsc);
            *(float4*)(smem + SK_OFF + r*512 + ((c ^ (r & 7)) << 4)) = v;
        }
        __syncthreads();
        const uint32_t aQ = sKb + rowA*512;
        #pragma unroll
        for (int ks = 0; ks < 16; ks++)
            ldm4(qf[ks], aQ + (((2*ks + hiA) ^ r8) << 4));
        __syncthreads();   // sK scratch free for K0
    }

    const float* kbase = kg + (uint32_t)(b*SEQ)*KSTR + hk*HD;
    const float* vbase = vg + (uint32_t)(b*SEQ)*KSTR + hk*HD;

    // ---- prologue: stage K0, V0 via cp.async ----
    {
        #pragma unroll
        for (int i = 0; i < 16; i++) {
            int idx = i*NTHREADS + tid;
            int r = idx >> 5, c = idx & 31;
            cpa16(sKb + r*512 + ((c ^ (r & 7)) << 4), kbase, (uint32_t)r*KSTR + c*4);
        }
        CP_COMMIT();
        #pragma unroll
        for (int i = 0; i < 16; i++) {
            int idx = i*NTHREADS + tid;
            int r = idx >> 5, c = idx & 31;
            cpa16(sVb + r*560 + c*16, vbase, (uint32_t)r*KSTR + c*4);
        }
        CP_COMMIT();
    }

    float o[16][4];
    #pragma unroll
    for (int nt = 0; nt < 16; nt++)
        o[nt][0] = o[nt][1] = o[nt][2] = o[nt][3] = 0.f;
    float l0 = 0.f, l8 = 0.f;

    const uint32_t bKbase = sKb + r8*512;

    for (int kt = 0; kt <= qt; kt++) {
        // K(kt) arrived (V(kt) may still be in flight)
        CP_WAIT(1);
        __syncthreads();

        // ---- QK^T: S(16x64 per warp) = Q_w @ K^T ----
        float s[8][4];
        #pragma unroll
        for (int j = 0; j < 8; j++)
            s[j][0] = s[j][1] = s[j][2] = s[j][3] = 0.f;
        #pragma unroll
        for (int kp = 0; kp < 8; kp++) {
            #pragma unroll
            for (int j = 0; j < 8; j++) {
                uint32_t B[4];
                ldm4(B, bKbase + j*4096 + (((4*kp + hiB) ^ r8) << 4));
                mma8(s[j], qf[2*kp],     B[0], B[1]);
                mma8(s[j], qf[2*kp + 1], B[2], B[3]);
            }
        }
        __syncthreads();   // all warps done reading sK

        // prefetch K(kt+1) into sK
        if (kt < qt) {
            const uint32_t koff0 = (uint32_t)(kt + 1)*BK*KSTR;
            #pragma unroll
            for (int i = 0; i < 16; i++) {
                int idx = i*NTHREADS + tid;
                int r = idx >> 5, c = idx & 31;
                cpa16(sKb + r*512 + ((c ^ (r & 7)) << 4), kbase, koff0 + (uint32_t)r*KSTR + c*4);
            }
            CP_COMMIT();
        }

        // ---- softmax (max-free): p = rna(exp2(s)); keep P in registers,
        //      pre-permuted (d0,d2,d1,d3) for direct use as PV A-fragments ----
        const bool diag = (kt == qt);
        const int rl0 = w*16 + g;
        uint32_t pr[8][4];
        #pragma unroll
        for (int j = 0; j < 8; j++) {
            float p0 = exp2f(s[j][0]);   // row g,   key 8j+2tig
            float p1 = exp2f(s[j][1]);   // row g,   key 8j+2tig+1
            float p2 = exp2f(s[j][2]);   // row g+8, key 8j+2tig
            float p3 = exp2f(s[j][3]);   // row g+8, key 8j+2tig+1
            if (diag) {
                int c = j*8 + 2*tig;
                if (c     > rl0)     p0 = 0.f;
                if (c + 1 > rl0)     p1 = 0.f;
                if (c     > rl0 + 8) p2 = 0.f;
                if (c + 1 > rl0 + 8) p3 = 0.f;
            }
            float r0 = tf32r(p0), r1 = tf32r(p1), r2 = tf32r(p2), r3 = tf32r(p3);
            l0 += r0 + r1;
            l8 += r2 + r3;
            pr[j][0] = __float_as_uint(r0);   // a0: row g,   sees key 2tig
            pr[j][1] = __float_as_uint(r2);   // a1: row g+8, sees key 2tig
            pr[j][2] = __float_as_uint(r1);   // a2: row g,   sees key 2tig+1
            pr[j][3] = __float_as_uint(r3);   // a3: row g+8, sees key 2tig+1
        }

        // V(kt) arrived (K(kt+1) may still be in flight)
        if (kt < qt) { CP_WAIT(1); } else { CP_WAIT(0); }
        __syncthreads();

        // ---- P·V: O += P_w(16x64) @ V(64x128), sigma-permuted V rows ----
        #pragma unroll
        for (int j = 0; j < 8; j++) {
            const char* vrow = smem + SV_OFF + (8*j + 2*tig)*560 + g*4;
            #pragma unroll
            for (int nt = 0; nt < 16; nt++) {
                uint32_t b0 = *(const uint32_t*)(vrow + nt*32);         // key 8j+2tig
                uint32_t b1 = *(const uint32_t*)(vrow + 560 + nt*32);   // key 8j+2tig+1
                mma8(o[nt], pr[j], b0, b1);
            }
        }
        __syncthreads();   // all warps done reading sV

        // prefetch V(kt+1) into sV
        if (kt < qt) {
            const uint32_t voff0 = (uint32_t)(kt + 1)*BK*KSTR;
            #pragma unroll
            for (int i = 0; i < 16; i++) {
                int idx = i*NTHREADS + tid;
                int r = idx >> 5, c = idx & 31;
                cpa16(sVb + r*560 + c*16, vbase, voff0 + (uint32_t)r*KSTR + c*4);
            }
            CP_COMMIT();
        }
    }

    // ---- epilogue: quad-reduce l, normalize, store ----
    l0 += __shfl_xor_sync(0xffffffffu, l0, 1);
    l0 += __shfl_xor_sync(0xffffffffu, l0, 2);
    l8 += __shfl_xor_sync(0xffffffffu, l8, 1);
    l8 += __shfl_xor_sync(0xffffffffu, l8, 2);
    const float i0 = 1.0f / l0;
    const float i8 = 1.0f / l8;

    float* og = outg + (uint32_t)(b*SEQ + q0 + w*16 + g)*QSTR + h*HD + 2*tig;
    #pragma unroll
    for (int nt = 0; nt < 16; nt++) {
        *(float2*)(og + nt*8)          = make_float2(o[nt][0]*i0, o[nt][1]*i0);
        *(float2*)(og + 8*QSTR + nt*8) = make_float2(o[nt][2]*i8, o[nt][3]*i8);
    }
}

extern "C" void kernel_launch(void* const* d_in, const int* in_sizes, int n_in,
                              void* d_out, int out_size) {
    const float* q = (const float*)d_in[0];
    const float* k = (const float*)d_in[1];
    const float* v = (const float*)d_in[2];
    float* out = (float*)d_out;

    cudaFuncSetAttribute(fattn_mma, cudaFuncAttributeMaxDynamicSharedMemorySize,
                         SMEM_BYTES);
    dim3 grid(SEQ / BQ, NH, 2);   // (32, 32, 2)
    fattn_mma<<<grid, NTHREADS, SMEM_BYTES>>>(q, k, v, out);
}

// round 9
// speedup vs baseline: 1.0388x; 1.0388x over previous
#include <cuda_runtime.h>
#include <cstdint>

// Causal GQA attention via warp-level mma.sync tf32 (plain sm_103 target).
// B=2, S=2048, H=32, HK=8 (rep 4), D=128. fp32 in/out.
// Max-free softmax; Q as register A-fragments; P stays in registers (QK C-frags
// re-fed as PV A-frags, sigma absorbed into V addressing).
// This round: fused per-8-key-chunk QK->softmax->PV loop, double-buffered K,
// 2 barriers/tile, occ=2 (RF-capped).

#define SEQ 2048
#define NH 32
#define NHK 8
#define HD 128
#define QSTR (NH*HD)    // 4096
#define KSTR (NHK*HD)   // 1024
#define BQ 64
#define BK 64
#define NTHREADS 128

// smem layout (bytes)
#define SK0_OFF 0                     // K buf 0: 64 rows x 512B, swizzled
#define SK1_OFF 32768                 // K buf 1
#define SV_OFF  65536                 // V: 64 rows x 560B (128f + pad), linear
#define SMEM_BYTES (SV_OFF + 64*560)  // 101376 ; 2 CTAs -> 202KB? no: per-CTA, 2x101376=202752 <= 227328

static __device__ __forceinline__ uint32_t smem_u32(const void* p){
    uint32_t a;
    asm("{ .reg .u64 t; cvta.to.shared.u64 t, %1; cvt.u32.u64 %0, t; }" : "=r"(a) : "l"(p));
    return a;
}
static __device__ __forceinline__ float tf32r(float x){
    uint32_t u;
    asm("cvt.rna.tf32.f32 %0, %1;" : "=r"(u) : "f"(x));
    return __uint_as_float(u);
}
static __device__ __forceinline__ void ldm4(uint32_t* r, uint32_t addr){
    asm volatile("ldmatrix.sync.aligned.m8n8.x4.shared.b16 {%0,%1,%2,%3}, [%4];"
                 : "=r"(r[0]), "=r"(r[1]), "=r"(r[2]), "=r"(r[3]) : "r"(addr));
}
static __device__ __forceinline__ void mma8(float* d, const uint32_t* a,
                                            uint32_t b0, uint32_t b1){
    asm volatile(
        "mma.sync.aligned.m16n8k8.row.col.f32.tf32.tf32.f32 "
        "{%0,%1,%2,%3}, {%4,%5,%6,%7}, {%8,%9}, {%0,%1,%2,%3};"
        : "+f"(d[0]), "+f"(d[1]), "+f"(d[2]), "+f"(d[3])
        : "r"(a[0]), "r"(a[1]), "r"(a[2]), "r"(a[3]), "r"(b0), "r"(b1));
}
static __device__ __forceinline__ void cpa16(uint32_t dst, const void* src){
    asm volatile("cp.async.cg.shared.global [%0], [%1], 16;" :: "r"(dst), "l"(src));
}
#define CP_COMMIT() asm volatile("cp.async.commit_group;")
#define CP_WAIT(N)  asm volatile("cp.async.wait_group %0;" :: "n"(N))

__global__ __launch_bounds__(NTHREADS, 2)
void fattn_mma(const float* __restrict__ qg, const float* __restrict__ kg,
               const float* __restrict__ vg, float* __restrict__ outg)
{
    extern __shared__ char smem[];
    const uint32_t smb = smem_u32(smem);
    const uint32_t sK0 = smb + SK0_OFF;
    const uint32_t sK1 = smb + SK1_OFF;
    const uint32_t sVb = smb + SV_OFF;

    const int tid  = threadIdx.x;
    const int lane = tid & 31;
    const int w    = tid >> 5;          // warp 0..3, owns q-rows 16w..16w+15
    const int g    = lane >> 2;
    const int tig  = lane & 3;
    const int mi   = lane >> 3;
    const int r8   = lane & 7;
    const int hiA  = mi >> 1;           // A-frag chunk offset (0/1)
    const int hiB  = lane >> 3;         // B-frag chunk offset (0..3)
    const int rowA = w*16 + (mi & 1)*8 + r8;

    const int qt = (int)(gridDim.x - 1 - blockIdx.x);   // heavy tiles first
    const int h  = blockIdx.y;
    const int b  = blockIdx.z;
    const int hk = h >> 2;
    const int q0 = qt * BQ;

    // staging index for this thread (shared by Q/K/V staging loops)
    // idx = i*128 + tid ; r = idx>>5, c = idx&31

    // ---- build Q A-fragments in registers (staged via sK0 as scratch) ----
    uint32_t qf[16][4];
    {
        const float qsc = 0.08838834764831845f * 1.4426950408889634f;
        const float* qs = qg + (size_t)(b*SEQ + q0)*QSTR + h*HD;
        #pragma unroll
        for (int i = 0; i < 16; i++) {
            int idx = i*NTHREADS + tid;
            int r = idx >> 5, c = idx & 31;
            float4 v = *(const float4*)(qs + (size_t)r*QSTR + c*4);
            v.x = tf32r(v.x*qsc); v.y = tf32r(v.y*qsc);
            v.z = tf32r(v.z*qsc); v.w = tf32r(v.w*qsc);
            *(float4*)(smem + SK0_OFF + r*512 + ((c ^ (r & 7)) << 4)) = v;
        }
        __syncthreads();
        const uint32_t aQ = sK0 + rowA*512;
        #pragma unroll
        for (int ks = 0; ks < 16; ks++)
            ldm4(qf[ks], aQ + (((2*ks + hiA) ^ r8) << 4));
        __syncthreads();   // sK0 scratch free for K0
    }

    const float* kbase = kg + (size_t)(b*SEQ)*KSTR + hk*HD;
    const float* vbase = vg + (size_t)(b*SEQ)*KSTR + hk*HD;

    // ---- prologue: stage K0 (buf0) and V0 via cp.async ----
    {
        #pragma unroll
        for (int i = 0; i < 16; i++) {
            int idx = i*NTHREADS + tid;
            int r = idx >> 5, c = idx & 31;
            cpa16(sK0 + r*512 + ((c ^ (r & 7)) << 4), kbase + (size_t)r*KSTR + c*4);
        }
        CP_COMMIT();
        #pragma unroll
        for (int i = 0; i < 16; i++) {
            int idx = i*NTHREADS + tid;
            int r = idx >> 5, c = idx & 31;
            cpa16(sVb + r*560 + c*16, vbase + (size_t)r*KSTR + c*4);
        }
        CP_COMMIT();
    }

    float o[16][4];
    #pragma unroll
    for (int nt = 0; nt < 16; nt++)
        o[nt][0] = o[nt][1] = o[nt][2] = o[nt][3] = 0.f;
    float l0 = 0.f, l8 = 0.f;

    for (int kt = 0; kt <= qt; kt++) {
        // prefetch K(kt+1) into the other K buffer (its prior readers finished
        // at the end-of-tile sync of kt-1; for kt=0 it's untouched)
        if (kt < qt) {
            const uint32_t dst = ((kt + 1) & 1) ? sK1 : sK0;
            const float* ksrc = kbase + (size_t)(kt + 1)*BK*KSTR;
            #pragma unroll
            for (int i = 0; i < 16; i++) {
                int idx = i*NTHREADS + tid;
                int r = idx >> 5, c = idx & 31;
                cpa16(dst + r*512 + ((c ^ (r & 7)) << 4), ksrc + (size_t)r*KSTR + c*4);
            }
            CP_COMMIT();
        }

        // K(kt) and V(kt) arrived; only K(kt+1) may remain in flight
        if (kt < qt) { CP_WAIT(1); } else { CP_WAIT(0); }
        __syncthreads();

        const uint32_t bKcur = ((kt & 1) ? sK1 : sK0) + r8*512;
        const bool diag = (kt == qt);
        const int rl0 = w*16 + g;

        // ---- fused per-8-key-chunk: QK(j) -> softmax(j) -> PV(j) ----
        #pragma unroll
        for (int j = 0; j < 8; j++) {
            // QK: s = Q_w(16x128) @ K[8 keys of chunk j]^T
            float s[4];
            s[0] = s[1] = s[2] = s[3] = 0.f;
            #pragma unroll
            for (int kp = 0; kp < 8; kp++) {
                uint32_t B[4];
                ldm4(B, bKcur + j*4096 + (((4*kp + hiB) ^ r8) << 4));
                mma8(s, qf[2*kp],     B[0], B[1]);
                mma8(s, qf[2*kp + 1], B[2], B[3]);
            }

            // softmax (max-free): p = rna(exp2(s)); pre-permute (d0,d2,d1,d3)
            float p0 = exp2f(s[0]);   // row g,   key 8j+2tig
            float p1 = exp2f(s[1]);   // row g,   key 8j+2tig+1
            float p2 = exp2f(s[2]);   // row g+8, key 8j+2tig
            float p3 = exp2f(s[3]);   // row g+8, key 8j+2tig+1
            if (diag) {
                int c = j*8 + 2*tig;
                if (c     > rl0)     p0 = 0.f;
                if (c + 1 > rl0)     p1 = 0.f;
                if (c     > rl0 + 8) p2 = 0.f;
                if (c + 1 > rl0 + 8) p3 = 0.f;
            }
            float r0 = tf32r(p0), r1 = tf32r(p1), r2 = tf32r(p2), r3 = tf32r(p3);
            l0 += r0 + r1;
            l8 += r2 + r3;
            uint32_t pr[4];
            pr[0] = __float_as_uint(r0);   // a0: row g,   sees key 2tig
            pr[1] = __float_as_uint(r2);   // a1: row g+8, sees key 2tig
            pr[2] = __float_as_uint(r1);   // a2: row g,   sees key 2tig+1
            pr[3] = __float_as_uint(r3);   // a3: row g+8, sees key 2tig+1

            // PV: O += P[:, chunk j] @ V[chunk j, :], sigma-permuted V rows
            const char* vrow = smem + SV_OFF + (8*j + 2*tig)*560 + g*4;
            #pragma unroll
            for (int nt = 0; nt < 16; nt++) {
                uint32_t b0 = *(const uint32_t*)(vrow + nt*32);         // key 8j+2tig
                uint32_t b1 = *(const uint32_t*)(vrow + 560 + nt*32);   // key 8j+2tig+1
                mma8(o[nt], pr, b0, b1);
            }
        }
        __syncthreads();   // all warps done reading sV (and K buf kt)

        // prefetch V(kt+1) into sV (readers of this tile are done)
        if (kt < qt) {
            const float* vsrc = vbase + (size_t)(kt + 1)*BK*KSTR;
            #pragma unroll
            for (int i = 0; i < 16; i++) {
                int idx = i*NTHREADS + tid;
                int r = idx >> 5, c = idx & 31;
                cpa16(sVb + r*560 + c*16, vsrc + (size_t)r*KSTR + c*4);
            }
            CP_COMMIT();
        }
    }

    // ---- epilogue: quad-reduce l, normalize, store ----
    l0 += __shfl_xor_sync(0xffffffffu, l0, 1);
    l0 += __shfl_xor_sync(0xffffffffu, l0, 2);
    l8 += __shfl_xor_sync(0xffffffffu, l8, 1);
    l8 += __shfl_xor_sync(0xffffffffu, l8, 2);
    const float i0 = 1.0f / l0;
    const float i8 = 1.0f / l8;

    float* og = outg + (size_t)(b*SEQ + q0 + w*16 + g)*QSTR + h*HD + 2*tig;
    #pragma unroll
    for (int nt = 0; nt < 16; nt++) {
        *(float2*)(og + nt*8)          = make_float2(o[nt][0]*i0, o[nt][1]*i0);
        *(float2*)(og + 8*QSTR + nt*8) = make_float2(o[nt][2]*i8, o[nt][3]*i8);
    }
}

extern "C" void kernel_launch(void* const* d_in, const int* in_sizes, int n_in,
                              void* d_out, int out_size) {
    const float* q = (const float*)d_in[0];
    const float* k = (const float*)d_in[1];
    const float* v = (const float*)d_in[2];
    float* out = (float*)d_out;

    cudaFuncSetAttribute(fattn_mma, cudaFuncAttributeMaxDynamicSharedMemorySize,
                         SMEM_BYTES);
    dim3 grid(SEQ / BQ, NH, 2);   // (32, 32, 2)
    fattn_mma<<<grid, NTHREADS, SMEM_BYTES>>>(q, k, v, out);
}